// round 1
// baseline (speedup 1.0000x reference)
#include <cuda_runtime.h>
#include <math.h>

// Problem constants
#define BB   2
#define NH   16
#define LL   2048
#define EE   1024
#define DD   1024
#define HDD  64
#define NDD  33      // 2*CLIP+1
#define BHH  (BB*NH)     // 32
#define MLL  (BB*LL)     // 4096
#define SCALE 0.03125f   // 1/sqrt(1024)

// ---------------------------------------------------------------------------
// Scratch (device globals: the sanctioned no-alloc path)
// ---------------------------------------------------------------------------
__device__ float g_qh[BHH * LL * HDD];     // (bh, l, hd)
__device__ float g_kh[BHH * LL * HDD];
__device__ float g_vh[BHH * LL * HDD];
__device__ float g_p [BHH * LL * NDD];     // rel-score lookup per (row, dist-class)
__device__ float g_w [BHH * LL * NDD];     // attn mass per dist-class
__device__ float g_o [MLL * DD];           // merged-head attention output
__device__ float g_s [134217728];          // (bh, q, k) scores / attn  (512 MiB)

// ---------------------------------------------------------------------------
// GEMM: out = relu(A @ W^T + bias).  A:(4096,1024) K-contig, W:(1024,1024) K-contig.
// MODE 0/1/2: write split-head layout into g_qh/g_kh/g_vh. MODE 3: A=g_o, flat out.
// 128x128x16 tiles, 256 threads, 8x8 per thread.
// ---------------------------------------------------------------------------
template<int MODE>
__global__ void __launch_bounds__(256, 2)
proj_gemm_kernel(const float* __restrict__ A, const float* __restrict__ W,
                 const float* __restrict__ bias, float* __restrict__ outp)
{
    __shared__ float As[16][132];
    __shared__ float Bs[16][132];
    const int K = EE;
    const int tid = threadIdx.x;
    const int tx = tid & 15, ty = tid >> 4;
    const int m0 = blockIdx.y * 128, n0 = blockIdx.x * 128;

    const float* Ap = (MODE == 3) ? g_o : A;
    const float* Abase = Ap + (size_t)m0 * K;
    const float* Wbase = W + (size_t)n0 * K;

    const int lr = tid >> 2;
    const int lk = (tid & 3) * 4;

    float acc[8][8];
    #pragma unroll
    for (int i = 0; i < 8; ++i)
        #pragma unroll
        for (int j = 0; j < 8; ++j) acc[i][j] = 0.f;

    for (int kt = 0; kt < K; kt += 16) {
        #pragma unroll
        for (int hh = 0; hh < 2; ++hh) {
            int r = lr + hh * 64;
            float4 va = *(const float4*)(Abase + (size_t)r * K + kt + lk);
            As[lk+0][r] = va.x; As[lk+1][r] = va.y; As[lk+2][r] = va.z; As[lk+3][r] = va.w;
            float4 vb = *(const float4*)(Wbase + (size_t)r * K + kt + lk);
            Bs[lk+0][r] = vb.x; Bs[lk+1][r] = vb.y; Bs[lk+2][r] = vb.z; Bs[lk+3][r] = vb.w;
        }
        __syncthreads();
        #pragma unroll
        for (int kk = 0; kk < 16; ++kk) {
            float a[8], b[8];
            *(float4*)(a)     = *(const float4*)&As[kk][ty * 8];
            *(float4*)(a + 4) = *(const float4*)&As[kk][ty * 8 + 4];
            *(float4*)(b)     = *(const float4*)&Bs[kk][tx * 8];
            *(float4*)(b + 4) = *(const float4*)&Bs[kk][tx * 8 + 4];
            #pragma unroll
            for (int i = 0; i < 8; ++i)
                #pragma unroll
                for (int j = 0; j < 8; ++j)
                    acc[i][j] = fmaf(a[i], b[j], acc[i][j]);
        }
        __syncthreads();
    }

    #pragma unroll
    for (int i = 0; i < 8; ++i) {
        int m = m0 + ty * 8 + i;
        int bidx = m >> 11;       // / 2048
        int l = m & 2047;
        #pragma unroll
        for (int j = 0; j < 8; ++j) {
            int n = n0 + tx * 8 + j;
            float vv = fmaxf(acc[i][j] + bias[n], 0.f);
            if (MODE == 3) {
                outp[(size_t)m * DD + n] = vv;
            } else {
                size_t idx = (((size_t)(bidx * NH + (n >> 6))) * LL + l) * HDD + (n & 63);
                if (MODE == 0) g_qh[idx] = vv;
                else if (MODE == 1) g_kh[idx] = vv;
                else g_vh[idx] = vv;
            }
        }
    }
}

// ---------------------------------------------------------------------------
// p[row][j] = sum_d qh[row][d] * rel_k[j][d]   (row = bh*L + q)
// ---------------------------------------------------------------------------
__global__ void __launch_bounds__(264)
pcompute_kernel(const float* __restrict__ rel_k)
{
    __shared__ float qs[8 * HDD];      // 8 rows
    __shared__ float rk[NDD * HDD];
    const int tid = threadIdx.y * 33 + threadIdx.x;
    const size_t row0 = (size_t)blockIdx.x * 8;

    for (int idx = tid; idx < NDD * HDD; idx += 264) rk[idx] = rel_k[idx];
    for (int idx = tid; idx < 8 * HDD;  idx += 264) qs[idx] = g_qh[row0 * HDD + idx];
    __syncthreads();

    const int j = threadIdx.x;
    const int r = threadIdx.y;
    float s = 0.f;
    #pragma unroll
    for (int d = 0; d < HDD; ++d)
        s = fmaf(qs[r * HDD + d], rk[j * HDD + d], s);
    g_p[(row0 + r) * NDD + j] = s;
}

// ---------------------------------------------------------------------------
// scores: S[bh][q][k] = (qh.kh + p[bh][q][clip(k-q)+16]) * SCALE
// 128x128 tiles over (q,k), K=64.
// ---------------------------------------------------------------------------
__global__ void __launch_bounds__(256, 2)
scores_kernel()
{
    __shared__ float As[16][132];
    __shared__ float Bs[16][132];
    const int tid = threadIdx.x;
    const int tx = tid & 15, ty = tid >> 4;
    const int bh = blockIdx.z;
    const int q0 = blockIdx.y * 128;
    const int k0 = blockIdx.x * 128;

    const float* Abase = g_qh + ((size_t)bh * LL + q0) * HDD;
    const float* Bbase = g_kh + ((size_t)bh * LL + k0) * HDD;
    const int lr = tid >> 2;
    const int lk = (tid & 3) * 4;

    float acc[8][8];
    #pragma unroll
    for (int i = 0; i < 8; ++i)
        #pragma unroll
        for (int j = 0; j < 8; ++j) acc[i][j] = 0.f;

    #pragma unroll
    for (int kt = 0; kt < HDD; kt += 16) {
        #pragma unroll
        for (int hh = 0; hh < 2; ++hh) {
            int r = lr + hh * 64;
            float4 va = *(const float4*)(Abase + (size_t)r * HDD + kt + lk);
            As[lk+0][r] = va.x; As[lk+1][r] = va.y; As[lk+2][r] = va.z; As[lk+3][r] = va.w;
            float4 vb = *(const float4*)(Bbase + (size_t)r * HDD + kt + lk);
            Bs[lk+0][r] = vb.x; Bs[lk+1][r] = vb.y; Bs[lk+2][r] = vb.z; Bs[lk+3][r] = vb.w;
        }
        __syncthreads();
        #pragma unroll
        for (int kk = 0; kk < 16; ++kk) {
            float a[8], b[8];
            *(float4*)(a)     = *(const float4*)&As[kk][ty * 8];
            *(float4*)(a + 4) = *(const float4*)&As[kk][ty * 8 + 4];
            *(float4*)(b)     = *(const float4*)&Bs[kk][tx * 8];
            *(float4*)(b + 4) = *(const float4*)&Bs[kk][tx * 8 + 4];
            #pragma unroll
            for (int i = 0; i < 8; ++i)
                #pragma unroll
                for (int j = 0; j < 8; ++j)
                    acc[i][j] = fmaf(a[i], b[j], acc[i][j]);
        }
        __syncthreads();
    }

    float* srow_base = g_s + (size_t)bh * LL * LL;
    const float* prow = g_p + (size_t)bh * LL * NDD;
    #pragma unroll
    for (int i = 0; i < 8; ++i) {
        int q = q0 + ty * 8 + i;
        #pragma unroll
        for (int j = 0; j < 8; ++j) {
            int kpos = k0 + tx * 8 + j;
            int dd = kpos - q;
            dd = dd < -16 ? -16 : (dd > 16 ? 16 : dd);
            float vv = (acc[i][j] + prow[q * NDD + dd + 16]) * SCALE;
            srow_base[(size_t)q * LL + kpos] = vv;
        }
    }
}

// ---------------------------------------------------------------------------
// softmax over k (2048) per row + distance-class mass w[row][0..32]
// ---------------------------------------------------------------------------
__global__ void __launch_bounds__(256)
softmax_w_kernel()
{
    const int row = blockIdx.x;            // bh*L + q
    const int q = row & (LL - 1);
    float* srow = g_s + (size_t)row * LL;
    const int tid = threadIdx.x;
    __shared__ float red[256];

    float vals[8];
    float m = -1e30f;
    #pragma unroll
    for (int i = 0; i < 8; ++i) {
        vals[i] = srow[tid + i * 256];
        m = fmaxf(m, vals[i]);
    }
    red[tid] = m; __syncthreads();
    #pragma unroll
    for (int s = 128; s >= 1; s >>= 1) {
        if (tid < s) red[tid] = fmaxf(red[tid], red[tid + s]);
        __syncthreads();
    }
    m = red[0]; __syncthreads();

    float sum = 0.f;
    #pragma unroll
    for (int i = 0; i < 8; ++i) {
        vals[i] = __expf(vals[i] - m);
        sum += vals[i];
    }
    red[tid] = sum; __syncthreads();
    #pragma unroll
    for (int s = 128; s >= 1; s >>= 1) {
        if (tid < s) red[tid] += red[tid + s];
        __syncthreads();
    }
    sum = red[0]; __syncthreads();
    const float inv = 1.f / sum;

    // zero the w row, then fill
    if (tid < NDD) g_w[(size_t)row * NDD + tid] = 0.f;
    __syncthreads();

    float w0 = 0.f, w32 = 0.f;
    #pragma unroll
    for (int i = 0; i < 8; ++i) {
        int k = tid + i * 256;
        float a = vals[i] * inv;
        srow[k] = a;
        int dd = k - q;
        if (dd <= -16)      w0  += a;
        else if (dd >= 16)  w32 += a;
        else                g_w[(size_t)row * NDD + dd + 16] = a;
    }
    red[tid] = w0; __syncthreads();
    #pragma unroll
    for (int s = 128; s >= 1; s >>= 1) {
        if (tid < s) red[tid] += red[tid + s];
        __syncthreads();
    }
    if (tid == 0) g_w[(size_t)row * NDD + 0] = red[0];
    __syncthreads();
    red[tid] = w32; __syncthreads();
    #pragma unroll
    for (int s = 128; s >= 1; s >>= 1) {
        if (tid < s) red[tid] += red[tid + s];
        __syncthreads();
    }
    if (tid == 0) g_w[(size_t)row * NDD + 32] = red[0];
}

// ---------------------------------------------------------------------------
// O[bh][q][d] = sum_k attn*vh + sum_j w[q][j]*rel_v[j][d]; write merged heads.
// Block: 128 q-rows x 64 d (all), K tiles of 16. 256 threads, 8x4 per thread.
// ---------------------------------------------------------------------------
__global__ void __launch_bounds__(256)
outk_kernel(const float* __restrict__ rel_v)
{
    __shared__ float As[16][132];
    __shared__ float Vs[16][64];
    __shared__ float ws[128 * NDD];   // 4224 floats
    __shared__ float rv[NDD * HDD];   // 2112 floats
    const int tid = threadIdx.x;
    const int tx = tid & 15, ty = tid >> 4;
    const int bh = blockIdx.z;
    const int q0 = blockIdx.x * 128;

    const float* Abase = g_s + ((size_t)bh * LL + q0) * LL;
    const float* Vbase = g_vh + (size_t)bh * LL * HDD;

    for (int idx = tid; idx < 128 * NDD; idx += 256)
        ws[idx] = g_w[((size_t)bh * LL + q0) * NDD + idx];
    for (int idx = tid; idx < NDD * HDD; idx += 256)
        rv[idx] = rel_v[idx];

    const int lr = tid >> 2;
    const int lk = (tid & 3) * 4;
    const int vr = tid >> 4;
    const int vc = (tid & 15) * 4;

    float acc[8][4];
    #pragma unroll
    for (int i = 0; i < 8; ++i)
        #pragma unroll
        for (int j = 0; j < 4; ++j) acc[i][j] = 0.f;

    for (int kt = 0; kt < LL; kt += 16) {
        #pragma unroll
        for (int hh = 0; hh < 2; ++hh) {
            int r = lr + hh * 64;
            float4 va = *(const float4*)(Abase + (size_t)r * LL + kt + lk);
            As[lk+0][r] = va.x; As[lk+1][r] = va.y; As[lk+2][r] = va.z; As[lk+3][r] = va.w;
        }
        float4 vv4 = *(const float4*)(Vbase + (size_t)(kt + vr) * HDD + vc);
        *(float4*)&Vs[vr][vc] = vv4;
        __syncthreads();
        #pragma unroll
        for (int kk = 0; kk < 16; ++kk) {
            float a[8], b[4];
            *(float4*)(a)     = *(const float4*)&As[kk][ty * 8];
            *(float4*)(a + 4) = *(const float4*)&As[kk][ty * 8 + 4];
            *(float4*)(b)     = *(const float4*)&Vs[kk][tx * 4];
            #pragma unroll
            for (int i = 0; i < 8; ++i)
                #pragma unroll
                for (int j = 0; j < 4; ++j)
                    acc[i][j] = fmaf(a[i], b[j], acc[i][j]);
        }
        __syncthreads();
    }

    const int bidx = bh >> 4;
    const int h = bh & 15;
    const int d0 = tx * 4;
    #pragma unroll
    for (int i = 0; i < 8; ++i) {
        int qrow = ty * 8 + i;
        int q = q0 + qrow;
        float r0 = acc[i][0], r1 = acc[i][1], r2 = acc[i][2], r3 = acc[i][3];
        for (int jj = 0; jj < NDD; ++jj) {
            float wv = ws[qrow * NDD + jj];
            const float* rvj = &rv[jj * HDD + d0];
            r0 = fmaf(wv, rvj[0], r0);
            r1 = fmaf(wv, rvj[1], r1);
            r2 = fmaf(wv, rvj[2], r2);
            r3 = fmaf(wv, rvj[3], r3);
        }
        float4 o4 = make_float4(r0, r1, r2, r3);
        *(float4*)&g_o[((size_t)bidx * LL + q) * DD + h * HDD + d0] = o4;
    }
}

// ---------------------------------------------------------------------------
// Launch
// ---------------------------------------------------------------------------
extern "C" void kernel_launch(void* const* d_in, const int* in_sizes, int n_in,
                              void* d_out, int out_size)
{
    const float* q     = (const float*)d_in[0];
    const float* k     = (const float*)d_in[1];
    const float* v     = (const float*)d_in[2];
    const float* Wq    = (const float*)d_in[3];
    const float* bq    = (const float*)d_in[4];
    const float* Wk    = (const float*)d_in[5];
    const float* bk    = (const float*)d_in[6];
    const float* Wv    = (const float*)d_in[7];
    const float* bv    = (const float*)d_in[8];
    const float* Wo    = (const float*)d_in[9];
    const float* bo    = (const float*)d_in[10];
    const float* rel_k = (const float*)d_in[11];
    const float* rel_v = (const float*)d_in[12];
    float* out = (float*)d_out;

    dim3 gproj(DD / 128, MLL / 128);             // (8, 32)
    proj_gemm_kernel<0><<<gproj, 256>>>(q, Wq, bq, nullptr);
    proj_gemm_kernel<1><<<gproj, 256>>>(k, Wk, bk, nullptr);
    proj_gemm_kernel<2><<<gproj, 256>>>(v, Wv, bv, nullptr);

    pcompute_kernel<<<BHH * LL / 8, dim3(33, 8)>>>(rel_k);

    dim3 gsc(LL / 128, LL / 128, BHH);           // (16, 16, 32)
    scores_kernel<<<gsc, 256>>>();

    softmax_w_kernel<<<BHH * LL, 256>>>();

    dim3 gout(LL / 128, 1, BHH);                 // (16, 1, 32)
    outk_kernel<<<gout, 256>>>(rel_v);

    proj_gemm_kernel<3><<<gproj, 256>>>(nullptr, Wo, bo, out);
}